// round 5
// baseline (speedup 1.0000x reference)
#include <cuda_runtime.h>
#include <math.h>

#define B_DIM   4096
#define C_DIM   5000
#define G4      1250                 // float4 groups per row
#define THREADS 1024
#define BLOCKS  148                  // one persistent block per SM, single wave
#define GPT     2                    // ceil(1250/1024)
#define MAX_LR  28                   // ceil(4096/148)

// cross-block column accumulators (zero at load; last block re-zeros each call)
__device__ float g_col_neg[C_DIM];
__device__ float g_col_pos[C_DIM];
__device__ float g_blk_rowloss[BLOCKS];
__device__ unsigned int g_done;      // zero-init; last block resets

__device__ __forceinline__ float softplus_f(float z) {
    return (z > 20.f) ? z : log1pf(__expf(z));
}

__global__ __launch_bounds__(THREADS, 1)
void twl_fused_kernel(const float* __restrict__ logits,
                      const int*   __restrict__ targets,
                      float* __restrict__ out) {
    __shared__ float s_n[MAX_LR * 32];
    __shared__ float s_p[MAX_LR * 32];
    __shared__ float s_loss[MAX_LR];
    __shared__ unsigned int s_ticket;
    __shared__ double s_red[32];

    const int t    = threadIdx.x;
    const int warp = t >> 5;
    const int lane = t & 31;

    // register-resident column partials: thread t owns float4-groups t, t+1024
    float cn[GPT][4], cp[GPT][4];
    #pragma unroll
    for (int j = 0; j < GPT; ++j)
        #pragma unroll
        for (int k = 0; k < 4; ++k) { cn[j][k] = 0.f; cp[j][k] = 0.f; }

    int lr = 0;
    for (int row = blockIdx.x; row < B_DIM; row += BLOCKS, ++lr) {
        const float4* __restrict__ lrow =
            reinterpret_cast<const float4*>(logits + (size_t)row * C_DIM);
        const int4* __restrict__ trow =
            reinterpret_cast<const int4*>(targets + (size_t)row * C_DIM);

        float rn = 0.f, rp = 0.f;

        #pragma unroll
        for (int j = 0; j < GPT; ++j) {
            const int g = t + j * THREADS;
            if (g < G4) {
                const float4 x  = lrow[g];
                const int4   tg = trow[g];

                #define PROC(XX, TT, K)                                       \
                do {                                                          \
                    const bool pos = ((TT) == 1);                             \
                    const bool neg = ((TT) == 0);                             \
                    const float a  = (XX) * (pos ? -0.25f : 1.0f);            \
                    const float e  = __expf(a);                               \
                    const float en = neg ? e : 0.f;                           \
                    const float ep = pos ? e : 0.f;                           \
                    rn += en; rp += ep;                                       \
                    cn[j][K] += en; cp[j][K] += ep;                           \
                } while (0)

                PROC(x.x, tg.x, 0);
                PROC(x.y, tg.y, 1);
                PROC(x.z, tg.z, 2);
                PROC(x.w, tg.w, 3);
                #undef PROC
            }
        }

        // warp-only reduce (no barrier): rows pipeline freely
        #pragma unroll
        for (int o = 16; o > 0; o >>= 1) {
            rn += __shfl_down_sync(0xffffffffu, rn, o);
            rp += __shfl_down_sync(0xffffffffu, rp, o);
        }
        if (lane == 0) {
            s_n[lr * 32 + warp] = rn;
            s_p[lr * 32 + warp] = rp;
        }
    }

    const int nrows = lr;

    // flush column partials via L2 REDs (no intermediate arrays, no 2nd kernel)
    #pragma unroll
    for (int j = 0; j < GPT; ++j) {
        const int g = t + j * THREADS;
        if (g < G4) {
            #pragma unroll
            for (int k = 0; k < 4; ++k) {
                atomicAdd(&g_col_neg[4 * g + k], cn[j][k]);
                atomicAdd(&g_col_pos[4 * g + k], cp[j][k]);
            }
        }
    }

    __syncthreads();

    // warp w finishes row w: 32 warp-partials -> row loss
    if (warp < nrows) {
        float vn = s_n[warp * 32 + lane];
        float vp = s_p[warp * 32 + lane];
        #pragma unroll
        for (int o = 16; o > 0; o >>= 1) {
            vn += __shfl_down_sync(0xffffffffu, vn, o);
            vp += __shfl_down_sync(0xffffffffu, vp, o);
        }
        if (lane == 0) {
            float loss = 0.f;
            if (vn > 0.f && vp > 0.f) {
                const float z = __logf(vn) + 4.f * __logf(vp);
                loss = softplus_f(z);
            }
            s_loss[warp] = loss;
        }
    }
    __syncthreads();
    if (warp == 0) {
        float v = (lane < nrows) ? s_loss[lane] : 0.f;
        #pragma unroll
        for (int o = 16; o > 0; o >>= 1)
            v += __shfl_down_sync(0xffffffffu, v, o);
        if (lane == 0) g_blk_rowloss[blockIdx.x] = v;
    }

    // make this block's REDs + rowloss store visible, then take a ticket
    __threadfence();
    __syncthreads();
    if (t == 0) s_ticket = atomicAdd(&g_done, 1u);
    __syncthreads();
    if (s_ticket != BLOCKS - 1) return;

    // ---- last block: finalize everything ----
    __threadfence();   // acquire: all other blocks' writes now visible

    // column losses over 5000 columns (L2-hot, 40 KB), then reset accumulators
    double loc = 0.0;
    for (int c = t; c < C_DIM; c += THREADS) {
        const float sn = g_col_neg[c];
        const float sp = g_col_pos[c];
        if (sn > 0.f && sp > 0.f) {
            const float z = __logf(sn) + 4.f * __logf(sp);
            loc += (double)softplus_f(z);
        }
        g_col_neg[c] = 0.f;          // reset for next graph replay
        g_col_pos[c] = 0.f;
    }
    // fold row losses in too (scaled to a common denominator later)
    double rs = 0.0;
    for (int b = t; b < BLOCKS; b += THREADS)
        rs += (double)g_blk_rowloss[b];

    // block-wide double reduce of (loc, rs) — pack via two rounds
    #pragma unroll
    for (int o = 16; o > 0; o >>= 1) {
        loc += __shfl_down_sync(0xffffffffu, loc, o);
        rs  += __shfl_down_sync(0xffffffffu, rs, o);
    }
    if (lane == 0) s_red[warp] = loc;
    __syncthreads();
    double loc_tot = 0.0;
    if (warp == 0) {
        double v = s_red[lane];
        #pragma unroll
        for (int o = 16; o > 0; o >>= 1)
            v += __shfl_down_sync(0xffffffffu, v, o);
        loc_tot = v;
    }
    __syncthreads();
    if (lane == 0) s_red[warp] = rs;
    __syncthreads();
    if (warp == 0 && lane == 0) {
        double r = 0.0;
        #pragma unroll
        for (int w = 0; w < 32; ++w) r += s_red[w];
        out[0] = (float)(0.5 * (r / (double)B_DIM + loc_tot / (double)C_DIM));
        g_done = 0u;                 // reset for next graph replay
    }
}

extern "C" void kernel_launch(void* const* d_in, const int* in_sizes, int n_in,
                              void* d_out, int out_size) {
    const float* logits  = (const float*)d_in[0];
    const int*   targets = (const int*)d_in[1];
    float* out = (float*)d_out;

    twl_fused_kernel<<<BLOCKS, THREADS>>>(logits, targets, out);
}

// round 8
// speedup vs baseline: 1.0679x; 1.0679x over previous
#include <cuda_runtime.h>
#include <math.h>

#define B_DIM   4096
#define C_DIM   5000
#define G4      1250                 // float4 groups per row
#define THREADS 640                  // 1250/640: near-perfect group balance
#define BLOCKS  296                  // 2 blocks per SM, single wave
#define GPT     2                    // groups per thread (t and t+640)
#define MAX_LR  14                   // ceil(4096/296)
#define NWARPS  (THREADS / 32)       // 20
#define NREP    4                    // column-accumulator replicas

// cross-block column accumulators (zero at load; last block re-zeros each call)
__device__ float g_col_neg[NREP][C_DIM];
__device__ float g_col_pos[NREP][C_DIM];
__device__ float g_blk_rowloss[BLOCKS];
__device__ unsigned int g_done;      // zero-init; last block resets

__device__ __forceinline__ float softplus_f(float z) {
    return (z > 20.f) ? z : log1pf(__expf(z));
}

__global__ __launch_bounds__(THREADS, 2)
void twl_fused_kernel(const float* __restrict__ logits,
                      const int*   __restrict__ targets,
                      float* __restrict__ out) {
    __shared__ float s_n[MAX_LR * NWARPS];
    __shared__ float s_p[MAX_LR * NWARPS];
    __shared__ float s_loss[MAX_LR];
    __shared__ unsigned int s_ticket;
    __shared__ double s_red[NWARPS];

    const int t    = threadIdx.x;
    const int warp = t >> 5;
    const int lane = t & 31;
    const int bid  = blockIdx.x;

    // register-resident column partials: thread t owns float4-groups t, t+640
    float cn[GPT][4], cp[GPT][4];
    #pragma unroll
    for (int j = 0; j < GPT; ++j)
        #pragma unroll
        for (int k = 0; k < 4; ++k) { cn[j][k] = 0.f; cp[j][k] = 0.f; }

    int lr = 0;
    for (int row = bid; row < B_DIM; row += BLOCKS, ++lr) {
        const float4* __restrict__ lrow =
            reinterpret_cast<const float4*>(logits + (size_t)row * C_DIM);
        const int4* __restrict__ trow =
            reinterpret_cast<const int4*>(targets + (size_t)row * C_DIM);

        float rn = 0.f, rp = 0.f;

        #pragma unroll
        for (int j = 0; j < GPT; ++j) {
            const int g = t + j * THREADS;
            if (g < G4) {
                const float4 x  = lrow[g];
                const int4   tg = trow[g];

                #define PROC(XX, TT, K)                                       \
                do {                                                          \
                    const bool pos = ((TT) == 1);                             \
                    const bool neg = ((TT) == 0);                             \
                    const float a  = (XX) * (pos ? -0.25f : 1.0f);            \
                    const float e  = __expf(a);                               \
                    const float en = neg ? e : 0.f;                           \
                    const float ep = pos ? e : 0.f;                           \
                    rn += en; rp += ep;                                       \
                    cn[j][K] += en; cp[j][K] += ep;                           \
                } while (0)

                PROC(x.x, tg.x, 0);
                PROC(x.y, tg.y, 1);
                PROC(x.z, tg.z, 2);
                PROC(x.w, tg.w, 3);
                #undef PROC
            }
        }

        // warp-only reduce (no barrier): rows pipeline freely
        #pragma unroll
        for (int o = 16; o > 0; o >>= 1) {
            rn += __shfl_down_sync(0xffffffffu, rn, o);
            rp += __shfl_down_sync(0xffffffffu, rp, o);
        }
        if (lane == 0) {
            s_n[lr * NWARPS + warp] = rn;
            s_p[lr * NWARPS + warp] = rp;
        }
    }

    const int nrows = lr;

    // flush column partials via L2 REDs into this block's replica
    {
        float* __restrict__ rep_n = g_col_neg[bid & (NREP - 1)];
        float* __restrict__ rep_p = g_col_pos[bid & (NREP - 1)];
        #pragma unroll
        for (int j = 0; j < GPT; ++j) {
            const int g = t + j * THREADS;
            if (g < G4) {
                #pragma unroll
                for (int k = 0; k < 4; ++k) {
                    atomicAdd(&rep_n[4 * g + k], cn[j][k]);
                    atomicAdd(&rep_p[4 * g + k], cp[j][k]);
                }
            }
        }
    }

    __syncthreads();

    // warp w finishes row w: NWARPS warp-partials -> row loss
    if (warp < nrows) {
        float vn = (lane < NWARPS) ? s_n[warp * NWARPS + lane] : 0.f;
        float vp = (lane < NWARPS) ? s_p[warp * NWARPS + lane] : 0.f;
        #pragma unroll
        for (int o = 16; o > 0; o >>= 1) {
            vn += __shfl_down_sync(0xffffffffu, vn, o);
            vp += __shfl_down_sync(0xffffffffu, vp, o);
        }
        if (lane == 0) {
            float loss = 0.f;
            if (vn > 0.f && vp > 0.f) {
                const float z = __logf(vn) + 4.f * __logf(vp);
                loss = softplus_f(z);
            }
            s_loss[warp] = loss;
        }
    }
    __syncthreads();
    if (warp == 0) {
        float v = (lane < nrows) ? s_loss[lane] : 0.f;
        #pragma unroll
        for (int o = 16; o > 0; o >>= 1)
            v += __shfl_down_sync(0xffffffffu, v, o);
        if (lane == 0) g_blk_rowloss[bid] = v;
    }

    // make this block's REDs + rowloss store visible, then take a ticket
    __threadfence();
    __syncthreads();
    if (t == 0) s_ticket = atomicAdd(&g_done, 1u);
    __syncthreads();
    if (s_ticket != BLOCKS - 1) return;

    // ---- last block: finalize everything ----
    __threadfence();   // acquire: all other blocks' writes now visible

    // column losses over 5000 columns (L2-hot), then reset accumulators
    double loc = 0.0;
    for (int c = t; c < C_DIM; c += THREADS) {
        float sn = 0.f, sp = 0.f;
        #pragma unroll
        for (int r = 0; r < NREP; ++r) {
            sn += g_col_neg[r][c];
            sp += g_col_pos[r][c];
            g_col_neg[r][c] = 0.f;   // reset for next graph replay
            g_col_pos[r][c] = 0.f;
        }
        if (sn > 0.f && sp > 0.f) {
            const float z = __logf(sn) + 4.f * __logf(sp);
            loc += (double)softplus_f(z);
        }
    }
    // fold row losses
    double rs = 0.0;
    for (int b = t; b < BLOCKS; b += THREADS)
        rs += (double)g_blk_rowloss[b];

    #pragma unroll
    for (int o = 16; o > 0; o >>= 1) {
        loc += __shfl_down_sync(0xffffffffu, loc, o);
        rs  += __shfl_down_sync(0xffffffffu, rs, o);
    }
    if (lane == 0) s_red[warp] = loc;
    __syncthreads();
    double loc_tot = 0.0;
    if (warp == 0 && lane == 0) {
        #pragma unroll
        for (int w = 0; w < NWARPS; ++w) loc_tot += s_red[w];
    }
    __syncthreads();
    if (lane == 0) s_red[warp] = rs;
    __syncthreads();
    if (warp == 0 && lane == 0) {
        double r = 0.0;
        #pragma unroll
        for (int w = 0; w < NWARPS; ++w) r += s_red[w];
        out[0] = (float)(0.5 * (r / (double)B_DIM + loc_tot / (double)C_DIM));
        g_done = 0u;                 // reset for next graph replay
    }
}

extern "C" void kernel_launch(void* const* d_in, const int* in_sizes, int n_in,
                              void* d_out, int out_size) {
    const float* logits  = (const float*)d_in[0];
    const int*   targets = (const int*)d_in[1];
    float* out = (float*)d_out;

    twl_fused_kernel<<<BLOCKS, THREADS>>>(logits, targets, out);
}

// round 9
// speedup vs baseline: 1.0716x; 1.0035x over previous
#include <cuda_runtime.h>
#include <math.h>

#define B_DIM   4096
#define C_DIM   5000
#define G4      1250                 // float4 groups per row
#define THREADS 640                  // 1250/640: near-perfect group balance
#define BLOCKS  296                  // 2 blocks per SM, single wave
#define GPT     2                    // groups per thread (t and t+640)
#define MAX_LR  14                   // ceil(4096/296)
#define NWARPS  (THREADS / 32)       // 20
#define NREP    4                    // column-accumulator replicas

// cross-block column accumulators (zero at load; last block re-zeros each call)
__device__ float g_col_neg[NREP][C_DIM];
__device__ float g_col_pos[NREP][C_DIM];
__device__ float g_blk_rowloss[BLOCKS];
__device__ unsigned int g_done;      // zero-init; last block resets

__device__ __forceinline__ float softplus_f(float z) {
    return (z > 20.f) ? z : log1pf(__expf(z));
}

// targets are guaranteed {0,1}: tf = exact 0.0f or 1.0f via IMAD (no I2F, no preds)
__device__ __forceinline__ void elem_f(float x, int tt, float& en, float& ep) {
    const float tf = __int_as_float(tt * 0x3f800000);
    const float m  = fmaf(tf, -1.25f, 1.0f);     // 1.0 (neg) or -0.25 (pos)
    const float e  = __expf(x * m);
    ep = e * tf;                                  // e if pos else 0
    en = e - ep;                                  // e if neg else 0
}

__global__ __launch_bounds__(THREADS, 2)
void twl_fused_kernel(const float* __restrict__ logits,
                      const int*   __restrict__ targets,
                      float* __restrict__ out) {
    __shared__ float s_n[MAX_LR * NWARPS];
    __shared__ float s_p[MAX_LR * NWARPS];
    __shared__ float s_loss[MAX_LR];
    __shared__ unsigned int s_ticket;
    __shared__ double s_red[NWARPS];

    const int t    = threadIdx.x;
    const int warp = t >> 5;
    const int lane = t & 31;
    const int bid  = blockIdx.x;

    const int  g0   = t;                  // always < 1250
    const int  g1   = t + THREADS;
    const bool has1 = (g1 < G4);

    // register-resident column partials
    float cn[GPT][4], cp[GPT][4];
    #pragma unroll
    for (int j = 0; j < GPT; ++j)
        #pragma unroll
        for (int k = 0; k < 4; ++k) { cn[j][k] = 0.f; cp[j][k] = 0.f; }

    // prologue: load group 0 of first row
    int row = bid;
    float4 x0; int4 t0;
    {
        const float4* lr0 = reinterpret_cast<const float4*>(logits + (size_t)row * C_DIM);
        const int4*   tr0 = reinterpret_cast<const int4*>(targets + (size_t)row * C_DIM);
        x0 = lr0[g0];
        t0 = tr0[g0];
    }

    int lr = 0;
    for (; row < B_DIM; row += BLOCKS, ++lr) {
        const float4* __restrict__ lrow =
            reinterpret_cast<const float4*>(logits + (size_t)row * C_DIM);
        const int4* __restrict__ trow =
            reinterpret_cast<const int4*>(targets + (size_t)row * C_DIM);

        // issue current row's group-1 load
        float4 x1; int4 t1;
        if (has1) { x1 = lrow[g1]; t1 = trow[g1]; }

        // prefetch next row's group-0 load (hidden behind this row's compute)
        const int nrow = row + BLOCKS;
        float4 px; int4 pt;
        if (nrow < B_DIM) {
            const float4* nl = reinterpret_cast<const float4*>(logits + (size_t)nrow * C_DIM);
            const int4*   nt = reinterpret_cast<const int4*>(targets + (size_t)nrow * C_DIM);
            px = nl[g0];
            pt = nt[g0];
        }

        float rn = 0.f, rp = 0.f;
        float en, ep;

        elem_f(x0.x, t0.x, en, ep); rn += en; rp += ep; cn[0][0] += en; cp[0][0] += ep;
        elem_f(x0.y, t0.y, en, ep); rn += en; rp += ep; cn[0][1] += en; cp[0][1] += ep;
        elem_f(x0.z, t0.z, en, ep); rn += en; rp += ep; cn[0][2] += en; cp[0][2] += ep;
        elem_f(x0.w, t0.w, en, ep); rn += en; rp += ep; cn[0][3] += en; cp[0][3] += ep;
        if (has1) {
            elem_f(x1.x, t1.x, en, ep); rn += en; rp += ep; cn[1][0] += en; cp[1][0] += ep;
            elem_f(x1.y, t1.y, en, ep); rn += en; rp += ep; cn[1][1] += en; cp[1][1] += ep;
            elem_f(x1.z, t1.z, en, ep); rn += en; rp += ep; cn[1][2] += en; cp[1][2] += ep;
            elem_f(x1.w, t1.w, en, ep); rn += en; rp += ep; cn[1][3] += en; cp[1][3] += ep;
        }

        // warp-only reduce (no barrier): rows pipeline freely
        #pragma unroll
        for (int o = 16; o > 0; o >>= 1) {
            rn += __shfl_down_sync(0xffffffffu, rn, o);
            rp += __shfl_down_sync(0xffffffffu, rp, o);
        }
        if (lane == 0) {
            s_n[lr * NWARPS + warp] = rn;
            s_p[lr * NWARPS + warp] = rp;
        }

        // rotate prefetch buffer
        x0 = px; t0 = pt;
    }

    const int nrows = lr;

    // flush column partials via L2 REDs into this block's replica
    {
        float* __restrict__ rep_n = g_col_neg[bid & (NREP - 1)];
        float* __restrict__ rep_p = g_col_pos[bid & (NREP - 1)];
        #pragma unroll
        for (int j = 0; j < GPT; ++j) {
            const int g = t + j * THREADS;
            if (g < G4) {
                #pragma unroll
                for (int k = 0; k < 4; ++k) {
                    atomicAdd(&rep_n[4 * g + k], cn[j][k]);
                    atomicAdd(&rep_p[4 * g + k], cp[j][k]);
                }
            }
        }
    }

    __syncthreads();

    // warp w finishes row w: NWARPS warp-partials -> row loss
    if (warp < nrows) {
        float vn = (lane < NWARPS) ? s_n[warp * NWARPS + lane] : 0.f;
        float vp = (lane < NWARPS) ? s_p[warp * NWARPS + lane] : 0.f;
        #pragma unroll
        for (int o = 16; o > 0; o >>= 1) {
            vn += __shfl_down_sync(0xffffffffu, vn, o);
            vp += __shfl_down_sync(0xffffffffu, vp, o);
        }
        if (lane == 0) {
            float loss = 0.f;
            if (vn > 0.f && vp > 0.f) {
                const float z = __logf(vn) + 4.f * __logf(vp);
                loss = softplus_f(z);
            }
            s_loss[warp] = loss;
        }
    }
    __syncthreads();
    if (warp == 0) {
        float v = (lane < nrows) ? s_loss[lane] : 0.f;
        #pragma unroll
        for (int o = 16; o > 0; o >>= 1)
            v += __shfl_down_sync(0xffffffffu, v, o);
        if (lane == 0) g_blk_rowloss[bid] = v;
    }

    // make this block's REDs + rowloss store visible, then take a ticket
    __threadfence();
    __syncthreads();
    if (t == 0) s_ticket = atomicAdd(&g_done, 1u);
    __syncthreads();
    if (s_ticket != BLOCKS - 1) return;

    // ---- last block: finalize everything ----
    __threadfence();   // acquire: all other blocks' writes now visible

    double loc = 0.0;
    for (int c = t; c < C_DIM; c += THREADS) {
        float sn = 0.f, sp = 0.f;
        #pragma unroll
        for (int r = 0; r < NREP; ++r) {
            sn += g_col_neg[r][c];
            sp += g_col_pos[r][c];
            g_col_neg[r][c] = 0.f;   // reset for next graph replay
            g_col_pos[r][c] = 0.f;
        }
        if (sn > 0.f && sp > 0.f) {
            const float z = __logf(sn) + 4.f * __logf(sp);
            loc += (double)softplus_f(z);
        }
    }
    double rs = 0.0;
    for (int b = t; b < BLOCKS; b += THREADS)
        rs += (double)g_blk_rowloss[b];

    #pragma unroll
    for (int o = 16; o > 0; o >>= 1) {
        loc += __shfl_down_sync(0xffffffffu, loc, o);
        rs  += __shfl_down_sync(0xffffffffu, rs, o);
    }
    if (lane == 0) s_red[warp] = loc;
    __syncthreads();
    double loc_tot = 0.0;
    if (warp == 0 && lane == 0) {
        #pragma unroll
        for (int w = 0; w < NWARPS; ++w) loc_tot += s_red[w];
    }
    __syncthreads();
    if (lane == 0) s_red[warp] = rs;
    __syncthreads();
    if (warp == 0 && lane == 0) {
        double r = 0.0;
        #pragma unroll
        for (int w = 0; w < NWARPS; ++w) r += s_red[w];
        out[0] = (float)(0.5 * (r / (double)B_DIM + loc_tot / (double)C_DIM));
        g_done = 0u;                 // reset for next graph replay
    }
}

extern "C" void kernel_launch(void* const* d_in, const int* in_sizes, int n_in,
                              void* d_out, int out_size) {
    const float* logits  = (const float*)d_in[0];
    const int*   targets = (const int*)d_in[1];
    float* out = (float*)d_out;

    twl_fused_kernel<<<BLOCKS, THREADS>>>(logits, targets, out);
}

// round 10
// speedup vs baseline: 1.0866x; 1.0140x over previous
#include <cuda_runtime.h>
#include <math.h>

#define B_DIM   4096
#define C_DIM   5000
#define G4      1250                 // float4 groups per row
#define THREADS 640
#define BLOCKS  296                  // 2 blocks per SM, single wave
#define GPT     2
#define MAX_LR  14                   // ceil(4096/296)
#define NWARPS  (THREADS / 32)       // 20
#define NREP    4                    // column-accumulator replicas

#define STAGE_BYTES   40000          // 1250*16 (logits) + 1250*16 (targets)
#define STAGE_L_OFF   0
#define STAGE_T_OFF   20000
#define SMEM_DYN      (2 * STAGE_BYTES)

// cross-block column accumulators (zero at load; last block re-zeros each call)
__device__ float g_col_neg[NREP][C_DIM];
__device__ float g_col_pos[NREP][C_DIM];
__device__ float g_blk_rowloss[BLOCKS];
__device__ unsigned int g_done;      // zero-init; last block resets

__device__ __forceinline__ float softplus_f(float z) {
    return (z > 20.f) ? z : log1pf(__expf(z));
}

// targets are {0,1}: tf = exact 0.0f/1.0f via IMAD (no I2F, no predicates)
__device__ __forceinline__ void elem_f(float x, int tt, float& en, float& ep) {
    const float tf = __int_as_float(tt * 0x3f800000);
    const float m  = fmaf(tf, -1.25f, 1.0f);     // 1.0 (neg) or -0.25 (pos)
    const float e  = __expf(x * m);
    ep = e * tf;
    en = e - ep;
}

__device__ __forceinline__ void cp16(void* dst_smem, const void* src) {
    const unsigned d = (unsigned)__cvta_generic_to_shared(dst_smem);
    asm volatile("cp.async.cg.shared.global [%0], [%1], 16;" :: "r"(d), "l"(src));
}
__device__ __forceinline__ void cp_commit() {
    asm volatile("cp.async.commit_group;");
}
template <int N>
__device__ __forceinline__ void cp_wait() {
    asm volatile("cp.async.wait_group %0;" :: "n"(N));
}

__global__ __launch_bounds__(THREADS, 2)
void twl_fused_kernel(const float* __restrict__ logits,
                      const int*   __restrict__ targets,
                      float* __restrict__ out) {
    extern __shared__ char smem_dyn[];
    __shared__ float s_n[MAX_LR * NWARPS];
    __shared__ float s_p[MAX_LR * NWARPS];
    __shared__ float s_loss[MAX_LR];
    __shared__ unsigned int s_ticket;
    __shared__ double s_red[NWARPS];

    const int t    = threadIdx.x;
    const int warp = t >> 5;
    const int lane = t & 31;
    const int bid  = blockIdx.x;

    const int  g0   = t;                  // always < 1250
    const int  g1   = t + THREADS;
    const bool has1 = (g1 < G4);

    float cn[GPT][4], cp[GPT][4];
    #pragma unroll
    for (int j = 0; j < GPT; ++j)
        #pragma unroll
        for (int k = 0; k < 4; ++k) { cn[j][k] = 0.f; cp[j][k] = 0.f; }

    // issue_row: copy one full row (logits + targets) into stage s
    auto issue_row = [&](int row, int s) {
        char* base = smem_dyn + s * STAGE_BYTES;
        float4* sL = reinterpret_cast<float4*>(base + STAGE_L_OFF);
        int4*   sT = reinterpret_cast<int4*>(base + STAGE_T_OFF);
        const float4* lrow = reinterpret_cast<const float4*>(logits + (size_t)row * C_DIM);
        const int4*   trow = reinterpret_cast<const int4*>(targets + (size_t)row * C_DIM);
        cp16(&sL[g0], &lrow[g0]);
        cp16(&sT[g0], &trow[g0]);
        if (has1) {
            cp16(&sL[g1], &lrow[g1]);
            cp16(&sT[g1], &trow[g1]);
        }
        cp_commit();
    };

    // prologue: stage 0 <- first row
    int row = bid;
    issue_row(row, 0);

    int s  = 0;
    int lr = 0;
    for (; row < B_DIM; row += BLOCKS, ++lr) {
        const int nrow = row + BLOCKS;
        if (nrow < B_DIM) {
            issue_row(nrow, s ^ 1);   // keep a full row always in flight
            cp_wait<1>();             // current row's group done
        } else {
            cp_wait<0>();
        }
        __syncthreads();

        const char* base = smem_dyn + s * STAGE_BYTES;
        const float4* sL = reinterpret_cast<const float4*>(base + STAGE_L_OFF);
        const int4*   sT = reinterpret_cast<const int4*>(base + STAGE_T_OFF);

        const float4 x0 = sL[g0];
        const int4   t0 = sT[g0];

        float rn = 0.f, rp = 0.f;
        float en, ep;

        elem_f(x0.x, t0.x, en, ep); rn += en; rp += ep; cn[0][0] += en; cp[0][0] += ep;
        elem_f(x0.y, t0.y, en, ep); rn += en; rp += ep; cn[0][1] += en; cp[0][1] += ep;
        elem_f(x0.z, t0.z, en, ep); rn += en; rp += ep; cn[0][2] += en; cp[0][2] += ep;
        elem_f(x0.w, t0.w, en, ep); rn += en; rp += ep; cn[0][3] += en; cp[0][3] += ep;
        if (has1) {
            const float4 x1 = sL[g1];
            const int4   t1 = sT[g1];
            elem_f(x1.x, t1.x, en, ep); rn += en; rp += ep; cn[1][0] += en; cp[1][0] += ep;
            elem_f(x1.y, t1.y, en, ep); rn += en; rp += ep; cn[1][1] += en; cp[1][1] += ep;
            elem_f(x1.z, t1.z, en, ep); rn += en; rp += ep; cn[1][2] += en; cp[1][2] += ep;
            elem_f(x1.w, t1.w, en, ep); rn += en; rp += ep; cn[1][3] += en; cp[1][3] += ep;
        }

        #pragma unroll
        for (int o = 16; o > 0; o >>= 1) {
            rn += __shfl_down_sync(0xffffffffu, rn, o);
            rp += __shfl_down_sync(0xffffffffu, rp, o);
        }
        if (lane == 0) {
            s_n[lr * NWARPS + warp] = rn;
            s_p[lr * NWARPS + warp] = rp;
        }

        __syncthreads();   // all warps done with stage s before it is re-filled
        s ^= 1;
    }

    const int nrows = lr;

    // flush column partials via L2 REDs into this block's replica
    {
        float* __restrict__ rep_n = g_col_neg[bid & (NREP - 1)];
        float* __restrict__ rep_p = g_col_pos[bid & (NREP - 1)];
        #pragma unroll
        for (int j = 0; j < GPT; ++j) {
            const int g = t + j * THREADS;
            if (g < G4) {
                #pragma unroll
                for (int k = 0; k < 4; ++k) {
                    atomicAdd(&rep_n[4 * g + k], cn[j][k]);
                    atomicAdd(&rep_p[4 * g + k], cp[j][k]);
                }
            }
        }
    }

    __syncthreads();

    if (warp < nrows) {
        float vn = (lane < NWARPS) ? s_n[warp * NWARPS + lane] : 0.f;
        float vp = (lane < NWARPS) ? s_p[warp * NWARPS + lane] : 0.f;
        #pragma unroll
        for (int o = 16; o > 0; o >>= 1) {
            vn += __shfl_down_sync(0xffffffffu, vn, o);
            vp += __shfl_down_sync(0xffffffffu, vp, o);
        }
        if (lane == 0) {
            float loss = 0.f;
            if (vn > 0.f && vp > 0.f) {
                const float z = __logf(vn) + 4.f * __logf(vp);
                loss = softplus_f(z);
            }
            s_loss[warp] = loss;
        }
    }
    __syncthreads();
    if (warp == 0) {
        float v = (lane < nrows) ? s_loss[lane] : 0.f;
        #pragma unroll
        for (int o = 16; o > 0; o >>= 1)
            v += __shfl_down_sync(0xffffffffu, v, o);
        if (lane == 0) g_blk_rowloss[bid] = v;
    }

    __threadfence();
    __syncthreads();
    if (t == 0) s_ticket = atomicAdd(&g_done, 1u);
    __syncthreads();
    if (s_ticket != BLOCKS - 1) return;

    // ---- last block: finalize ----
    __threadfence();

    double loc = 0.0;
    for (int c = t; c < C_DIM; c += THREADS) {
        float sn = 0.f, sp = 0.f;
        #pragma unroll
        for (int r = 0; r < NREP; ++r) {
            sn += g_col_neg[r][c];
            sp += g_col_pos[r][c];
            g_col_neg[r][c] = 0.f;
            g_col_pos[r][c] = 0.f;
        }
        if (sn > 0.f && sp > 0.f) {
            const float z = __logf(sn) + 4.f * __logf(sp);
            loc += (double)softplus_f(z);
        }
    }
    double rs = 0.0;
    for (int b = t; b < BLOCKS; b += THREADS)
        rs += (double)g_blk_rowloss[b];

    #pragma unroll
    for (int o = 16; o > 0; o >>= 1) {
        loc += __shfl_down_sync(0xffffffffu, loc, o);
        rs  += __shfl_down_sync(0xffffffffu, rs, o);
    }
    if (lane == 0) s_red[warp] = loc;
    __syncthreads();
    double loc_tot = 0.0;
    if (warp == 0 && lane == 0) {
        #pragma unroll
        for (int w = 0; w < NWARPS; ++w) loc_tot += s_red[w];
    }
    __syncthreads();
    if (lane == 0) s_red[warp] = rs;
    __syncthreads();
    if (warp == 0 && lane == 0) {
        double r = 0.0;
        #pragma unroll
        for (int w = 0; w < NWARPS; ++w) r += s_red[w];
        out[0] = (float)(0.5 * (r / (double)B_DIM + loc_tot / (double)C_DIM));
        g_done = 0u;
    }
}

extern "C" void kernel_launch(void* const* d_in, const int* in_sizes, int n_in,
                              void* d_out, int out_size) {
    const float* logits  = (const float*)d_in[0];
    const int*   targets = (const int*)d_in[1];
    float* out = (float*)d_out;

    cudaFuncSetAttribute(twl_fused_kernel,
                         cudaFuncAttributeMaxDynamicSharedMemorySize, SMEM_DYN);
    twl_fused_kernel<<<BLOCKS, THREADS, SMEM_DYN>>>(logits, targets, out);
}